// round 16
// baseline (speedup 1.0000x reference)
#include <cuda_runtime.h>
#include <cuda_fp16.h>

#define NUM_USERS 100000
#define NUM_ITEMS 50000
#define NN        (NUM_USERS + NUM_ITEMS)   // 150000
#define EMB       64
#define NBIC      20000
#define E_ADJ_MAX 1200000
#define E_HV_MAX  400000
#define E_HU_MAX  400000

#define CNT_ADJ_OFF 0
#define CNT_HV_OFF  (NN)
#define CNT_HU_OFF  (NN + NBIC)
#define CNT_TOT     (NN + NBIC + NUM_USERS)      // 270000

#define RP_ADJ_OFF 0
#define RP_HV_OFF  (NN + 1)
#define RP_HU_OFF  (NN + 1 + NBIC + 1)
#define RP_TOT     (NN + NBIC + NUM_USERS + 3)

#define NB_ADJ 147
#define NB_HV  20
#define NB_HU  98
#define NB_TOT (NB_ADJ + NB_HV + NB_HU)          // 265

#define NCONV (NN * (EMB / 4))                   // float4 count for e0 conversion

// ---------------- small helpers ----------------
__device__ __forceinline__ unsigned h2u(__half2 h) {
    return *reinterpret_cast<unsigned*>(&h);
}
__device__ __forceinline__ float2 u2f2(unsigned u) {
    return __half22float2(*reinterpret_cast<__half2*>(&u));
}

// ---------------- static device scratch ----------------
__device__ __align__(16) __half g_e0h[NN * EMB];     // fp16 concat(user,item)
__device__ __align__(16) __half g_eah[NN * EMB];
__device__ __align__(16) __half g_ebh[NN * EMB];
__device__ __align__(16) __half g_bich[NBIC * EMB];
__device__ __align__(16) float  g_ul[NUM_USERS * EMB];

__device__ int  g_cnt[CNT_TOT];
__device__ int  g_rp[RP_TOT];
__device__ int  g_bsum[NB_TOT];

__device__ int2 g_ep_adj[E_ADJ_MAX];
__device__ int2 g_ep_hv[E_HV_MAX];
__device__ int2 g_ep_hu[E_HU_MAX];

// ---------------- CSR build (compact, 4-edge ILP) ----------------

// 4 edges per thread: histogram; conversion rides in trailing threads
__global__ void k_hist_conv(const int* __restrict__ adj_row,
                            const int* __restrict__ hv_row,
                            const int* __restrict__ hu_row,
                            const float4* __restrict__ user4,
                            const float4* __restrict__ item4,
                            int e_adj, int e_hv, int e_hu,
                            int na4, int nv4, int nu4) {
    int i = blockIdx.x * blockDim.x + threadIdx.x;
    if (i < na4) {
        int b = i * 4;
        if (b + 3 < e_adj) {
            int4 r = *(const int4*)(adj_row + b);
            atomicAdd(&g_cnt[CNT_ADJ_OFF + r.x], 1);
            atomicAdd(&g_cnt[CNT_ADJ_OFF + r.y], 1);
            atomicAdd(&g_cnt[CNT_ADJ_OFF + r.z], 1);
            atomicAdd(&g_cnt[CNT_ADJ_OFF + r.w], 1);
        } else {
            for (int j = b; j < e_adj; j++) atomicAdd(&g_cnt[CNT_ADJ_OFF + adj_row[j]], 1);
        }
    } else if (i < na4 + nv4) {
        int b = (i - na4) * 4;
        if (b + 3 < e_hv) {
            int4 r = *(const int4*)(hv_row + b);
            atomicAdd(&g_cnt[CNT_HV_OFF + r.x], 1);
            atomicAdd(&g_cnt[CNT_HV_OFF + r.y], 1);
            atomicAdd(&g_cnt[CNT_HV_OFF + r.z], 1);
            atomicAdd(&g_cnt[CNT_HV_OFF + r.w], 1);
        } else {
            for (int j = b; j < e_hv; j++) atomicAdd(&g_cnt[CNT_HV_OFF + hv_row[j]], 1);
        }
    } else if (i < na4 + nv4 + nu4) {
        int b = (i - na4 - nv4) * 4;
        if (b + 3 < e_hu) {
            int4 r = *(const int4*)(hu_row + b);
            atomicAdd(&g_cnt[CNT_HU_OFF + r.x], 1);
            atomicAdd(&g_cnt[CNT_HU_OFF + r.y], 1);
            atomicAdd(&g_cnt[CNT_HU_OFF + r.z], 1);
            atomicAdd(&g_cnt[CNT_HU_OFF + r.w], 1);
        } else {
            for (int j = b; j < e_hu; j++) atomicAdd(&g_cnt[CNT_HU_OFF + hu_row[j]], 1);
        }
    } else {
        int j = i - na4 - nv4 - nu4;
        if (j < NCONV) {
            const int n4u = NUM_USERS * (EMB / 4);
            float4 v = (j < n4u) ? user4[j] : item4[j - n4u];
            uint2 hh;
            hh.x = h2u(__float22half2_rn(make_float2(v.x, v.y)));
            hh.y = h2u(__float22half2_rn(make_float2(v.z, v.w)));
            ((uint2*)g_e0h)[j] = hh;
        }
    }
}

__device__ __forceinline__ void seg_map(int b, int& cnt_off, int& n, int& local,
                                        int& seg_b0, int& rp_off) {
    if (b < NB_ADJ) {
        cnt_off = CNT_ADJ_OFF; n = NN;        local = b;                  seg_b0 = 0;               rp_off = RP_ADJ_OFF;
    } else if (b < NB_ADJ + NB_HV) {
        cnt_off = CNT_HV_OFF;  n = NBIC;      local = b - NB_ADJ;         seg_b0 = NB_ADJ;          rp_off = RP_HV_OFF;
    } else {
        cnt_off = CNT_HU_OFF;  n = NUM_USERS; local = b - NB_ADJ - NB_HV; seg_b0 = NB_ADJ + NB_HV;  rp_off = RP_HU_OFF;
    }
}

__global__ void k_blocksum_all() {
    __shared__ int sm[256];
    int cnt_off, n, local, seg_b0, rp_off;
    seg_map(blockIdx.x, cnt_off, n, local, seg_b0, rp_off);
    int t = threadIdx.x;
    int base = local * 1024 + t * 4;
    int s = 0;
    #pragma unroll
    for (int i = 0; i < 4; i++) { int idx = base + i; if (idx < n) s += g_cnt[cnt_off + idx]; }
    sm[t] = s; __syncthreads();
    for (int o = 128; o > 0; o >>= 1) {
        if (t < o) sm[t] += sm[t + o];
        __syncthreads();
    }
    if (t == 0) g_bsum[blockIdx.x] = sm[0];
}

__global__ void k_scan_chunk_all(int e_adj, int e_hv, int e_hu) {
    __shared__ int sm[256];
    int b = blockIdx.x;
    int cnt_off, n, local, seg_b0, rp_off;
    seg_map(b, cnt_off, n, local, seg_b0, rp_off);
    int ne = (b < NB_ADJ) ? e_adj : (b < NB_ADJ + NB_HV) ? e_hv : e_hu;

    int t = threadIdx.x;

    int pv = (t < local) ? g_bsum[seg_b0 + t] : 0;
    sm[t] = pv; __syncthreads();
    for (int o = 128; o > 0; o >>= 1) {
        if (t < o) sm[t] += sm[t + o];
        __syncthreads();
    }
    int blk_prefix = sm[0];
    __syncthreads();

    int base = local * 1024 + t * 4;
    int c0 = 0, c1 = 0, c2 = 0, c3 = 0;
    if (base + 0 < n) c0 = g_cnt[cnt_off + base + 0];
    if (base + 1 < n) c1 = g_cnt[cnt_off + base + 1];
    if (base + 2 < n) c2 = g_cnt[cnt_off + base + 2];
    if (base + 3 < n) c3 = g_cnt[cnt_off + base + 3];
    int tot = c0 + c1 + c2 + c3;
    sm[t] = tot; __syncthreads();
    for (int o = 1; o < 256; o <<= 1) {
        int x = (t >= o) ? sm[t - o] : 0;
        __syncthreads();
        sm[t] += x;
        __syncthreads();
    }
    int pre = sm[t] - tot + blk_prefix;
    int p0 = pre, p1 = pre + c0, p2 = p1 + c1, p3 = p2 + c2;
    if (base + 0 < n) { g_rp[rp_off + base + 0] = p0; g_cnt[cnt_off + base + 0] = p0; }
    if (base + 1 < n) { g_rp[rp_off + base + 1] = p1; g_cnt[cnt_off + base + 1] = p1; }
    if (base + 2 < n) { g_rp[rp_off + base + 2] = p2; g_cnt[cnt_off + base + 2] = p2; }
    if (base + 3 < n) { g_rp[rp_off + base + 3] = p3; g_cnt[cnt_off + base + 3] = p3; }
    if (local == 0 && t == 0) g_rp[rp_off + n] = ne;
}

// 4 edges per thread scatter with vector loads
__global__ void k_scatter_all(const int* __restrict__ adj_row, const int* __restrict__ adj_col,
                              const float* __restrict__ adj_val,
                              const int* __restrict__ hv_row, const int* __restrict__ hv_col,
                              const float* __restrict__ hv_val,
                              const int* __restrict__ hu_row, const int* __restrict__ hu_col,
                              const float* __restrict__ hu_val,
                              int e_adj, int e_hv, int e_hu,
                              int na4, int nv4, int nu4) {
    int i = blockIdx.x * blockDim.x + threadIdx.x;
    if (i < na4) {
        int b = i * 4;
        if (b + 3 < e_adj) {
            int4 r = *(const int4*)(adj_row + b);
            int4 c = *(const int4*)(adj_col + b);
            float4 v = *(const float4*)(adj_val + b);
            int p0 = atomicAdd(&g_cnt[CNT_ADJ_OFF + r.x], 1);
            int p1 = atomicAdd(&g_cnt[CNT_ADJ_OFF + r.y], 1);
            int p2 = atomicAdd(&g_cnt[CNT_ADJ_OFF + r.z], 1);
            int p3 = atomicAdd(&g_cnt[CNT_ADJ_OFF + r.w], 1);
            g_ep_adj[p0] = make_int2(c.x, __float_as_int(v.x));
            g_ep_adj[p1] = make_int2(c.y, __float_as_int(v.y));
            g_ep_adj[p2] = make_int2(c.z, __float_as_int(v.z));
            g_ep_adj[p3] = make_int2(c.w, __float_as_int(v.w));
        } else {
            for (int j = b; j < e_adj; j++) {
                int p = atomicAdd(&g_cnt[CNT_ADJ_OFF + adj_row[j]], 1);
                g_ep_adj[p] = make_int2(adj_col[j], __float_as_int(adj_val[j]));
            }
        }
    } else if (i < na4 + nv4) {
        int b = (i - na4) * 4;
        if (b + 3 < e_hv) {
            int4 r = *(const int4*)(hv_row + b);
            int4 c = *(const int4*)(hv_col + b);
            float4 v = *(const float4*)(hv_val + b);
            int p0 = atomicAdd(&g_cnt[CNT_HV_OFF + r.x], 1);
            int p1 = atomicAdd(&g_cnt[CNT_HV_OFF + r.y], 1);
            int p2 = atomicAdd(&g_cnt[CNT_HV_OFF + r.z], 1);
            int p3 = atomicAdd(&g_cnt[CNT_HV_OFF + r.w], 1);
            g_ep_hv[p0] = make_int2(c.x, __float_as_int(v.x));
            g_ep_hv[p1] = make_int2(c.y, __float_as_int(v.y));
            g_ep_hv[p2] = make_int2(c.z, __float_as_int(v.z));
            g_ep_hv[p3] = make_int2(c.w, __float_as_int(v.w));
        } else {
            for (int j = b; j < e_hv; j++) {
                int p = atomicAdd(&g_cnt[CNT_HV_OFF + hv_row[j]], 1);
                g_ep_hv[p] = make_int2(hv_col[j], __float_as_int(hv_val[j]));
            }
        }
    } else if (i < na4 + nv4 + nu4) {
        int b = (i - na4 - nv4) * 4;
        if (b + 3 < e_hu) {
            int4 r = *(const int4*)(hu_row + b);
            int4 c = *(const int4*)(hu_col + b);
            float4 v = *(const float4*)(hu_val + b);
            int p0 = atomicAdd(&g_cnt[CNT_HU_OFF + r.x], 1);
            int p1 = atomicAdd(&g_cnt[CNT_HU_OFF + r.y], 1);
            int p2 = atomicAdd(&g_cnt[CNT_HU_OFF + r.z], 1);
            int p3 = atomicAdd(&g_cnt[CNT_HU_OFF + r.w], 1);
            g_ep_hu[p0] = make_int2(c.x, __float_as_int(v.x));
            g_ep_hu[p1] = make_int2(c.y, __float_as_int(v.y));
            g_ep_hu[p2] = make_int2(c.z, __float_as_int(v.z));
            g_ep_hu[p3] = make_int2(c.w, __float_as_int(v.w));
        } else {
            for (int j = b; j < e_hu; j++) {
                int p = atomicAdd(&g_cnt[CNT_HU_OFF + hu_row[j]], 1);
                g_ep_hu[p] = make_int2(hu_col[j], __float_as_int(hu_val[j]));
            }
        }
    }
}

// ---------------- chunked half-warp fp16-gather SpMM (fp32 accum) ----------------

__device__ __forceinline__ void h4fma(float4& a, float v, uint2 q) {
    float2 f0 = u2f2(q.x);
    float2 f1 = u2f2(q.y);
    a.x += v * f0.x; a.y += v * f0.y; a.z += v * f1.x; a.w += v * f1.y;
}

__device__ __forceinline__ void f4comb(float4& a) {
    a.x += __shfl_xor_sync(0xffffffffu, a.x, 16);
    a.y += __shfl_xor_sync(0xffffffffu, a.y, 16);
    a.z += __shfl_xor_sync(0xffffffffu, a.z, 16);
    a.w += __shfl_xor_sync(0xffffffffu, a.w, 16);
}

__device__ __forceinline__ float4 spmm_row_h(const int2* __restrict__ ep, int s, int e,
                                             const __half* __restrict__ xh,
                                             int h, int l16, float* deg_out) {
    float4 acc = make_float4(0.f, 0.f, 0.f, 0.f);
    float deg = 0.f;
    const int2 zz = make_int2(0, 0);
    for (int c = s + h; c < e; c += 8) {
        int2 cv0 = ep[c];
        int2 cv1 = (c + 2 < e) ? ep[c + 2] : zz;
        int2 cv2 = (c + 4 < e) ? ep[c + 4] : zz;
        int2 cv3 = (c + 6 < e) ? ep[c + 6] : zz;
        uint2 q0 = ((const uint2*)(xh + (size_t)cv0.x * EMB))[l16];
        uint2 q1 = ((const uint2*)(xh + (size_t)cv1.x * EMB))[l16];
        uint2 q2 = ((const uint2*)(xh + (size_t)cv2.x * EMB))[l16];
        uint2 q3 = ((const uint2*)(xh + (size_t)cv3.x * EMB))[l16];
        float v0 = __int_as_float(cv0.y), v1 = __int_as_float(cv1.y);
        float v2 = __int_as_float(cv2.y), v3 = __int_as_float(cv3.y);
        deg += (v0 + v1) + (v2 + v3);
        h4fma(acc, v0, q0);
        h4fma(acc, v1, q1);
        h4fma(acc, v2, q2);
        h4fma(acc, v3, q3);
    }
    if (deg_out) *deg_out = deg;
    return acc;
}

__device__ __forceinline__ void store_h4(__half* dst, int l16, float4 a) {
    uint2 hh;
    hh.x = h2u(__float22half2_rn(make_float2(a.x, a.y)));
    hh.y = h2u(__float22half2_rn(make_float2(a.z, a.w)));
    ((uint2*)dst)[l16] = hh;
}

// ---------------- phase 1: adj1 + hv (both gather g_e0h) ----------------
__global__ void __launch_bounds__(256, 6)
k_phase1() {
    int r = blockIdx.x * 8 + (threadIdx.x >> 5);
    int lane = threadIdx.x & 31;
    int h = lane >> 4, l16 = lane & 15;

    if (r < NN) {
        int s = g_rp[RP_ADJ_OFF + r], e = g_rp[RP_ADJ_OFF + r + 1];
        float4 acc = spmm_row_h(g_ep_adj, s, e, g_e0h, h, l16, nullptr);
        f4comb(acc);
        if (h == 0) store_h4(g_eah + (size_t)r * EMB, l16, acc);
    } else if (r < NN + NBIC) {
        int rr = r - NN;
        int s = g_rp[RP_HV_OFF + rr], e = g_rp[RP_HV_OFF + rr + 1];
        float deg;
        float4 acc = spmm_row_h(g_ep_hv, s, e, g_e0h + (size_t)NUM_USERS * EMB, h, l16, &deg);
        f4comb(acc);
        deg += __shfl_xor_sync(0xffffffffu, deg, 16);
        if (h == 0) {
            float inv = (deg == 0.f) ? 1.f : (1.f / deg);
            acc.x *= inv; acc.y *= inv; acc.z *= inv; acc.w *= inv;
            store_h4(g_bich + (size_t)rr * EMB, l16, acc);
        }
    }
}

// ---------------- phase 2: adj2 + hu ----------------
__global__ void __launch_bounds__(256, 6)
k_phase2(float* __restrict__ ul) {
    int r = blockIdx.x * 8 + (threadIdx.x >> 5);
    int lane = threadIdx.x & 31;
    int h = lane >> 4, l16 = lane & 15;

    if (r < NN) {
        int s = g_rp[RP_ADJ_OFF + r], e = g_rp[RP_ADJ_OFF + r + 1];
        float4 acc = spmm_row_h(g_ep_adj, s, e, g_eah, h, l16, nullptr);
        f4comb(acc);
        if (h == 0) store_h4(g_ebh + (size_t)r * EMB, l16, acc);
    } else if (r < NN + NUM_USERS) {
        int rr = r - NN;
        int s = g_rp[RP_HU_OFF + rr], e = g_rp[RP_HU_OFF + rr + 1];
        float deg;
        float4 acc = spmm_row_h(g_ep_hu, s, e, g_bich, h, l16, &deg);
        f4comb(acc);
        deg += __shfl_xor_sync(0xffffffffu, deg, 16);
        if (h == 0) {
            float inv = (deg == 0.f) ? 1.f : (1.f / deg);
            acc.x *= inv; acc.y *= inv; acc.z *= inv; acc.w *= inv;
            ((float4*)(ul + (size_t)rr * EMB))[l16] = acc;
        }
    }
}

// ---------------- phase 3: adj3 + epilogue + cnt re-zero ----------------
__global__ void __launch_bounds__(256, 6)
k_phase3(const float* __restrict__ user, const float* __restrict__ item,
         const float* __restrict__ ul, float* __restrict__ out) {
    int gtid = blockIdx.x * blockDim.x + threadIdx.x;
    if (gtid < CNT_TOT) g_cnt[gtid] = 0;   // reset for next call

    int r = blockIdx.x * 8 + (threadIdx.x >> 5);
    if (r >= NN) return;
    int lane = threadIdx.x & 31;
    int h = lane >> 4, l16 = lane & 15;
    int s = g_rp[RP_ADJ_OFF + r], e = g_rp[RP_ADJ_OFF + r + 1];
    float4 acc = spmm_row_h(g_ep_adj, s, e, g_ebh, h, l16, nullptr);
    f4comb(acc);
    if (h == 0) {
        const float4* base = (const float4*)(r < NUM_USERS ? user + (size_t)r * EMB
                                                           : item + (size_t)(r - NUM_USERS) * EMB);
        float4 b0 = base[l16];
        uint2 qa = ((const uint2*)(g_eah + (size_t)r * EMB))[l16];
        uint2 qb = ((const uint2*)(g_ebh + (size_t)r * EMB))[l16];
        float2 a0 = u2f2(qa.x);
        float2 a1 = u2f2(qa.y);
        float2 c0 = u2f2(qb.x);
        float2 c1 = u2f2(qb.y);
        float4 o;
        o.x = 0.25f * (b0.x + a0.x + c0.x + acc.x);
        o.y = 0.25f * (b0.y + a0.y + c0.y + acc.y);
        o.z = 0.25f * (b0.z + a1.x + c1.x + acc.z);
        o.w = 0.25f * (b0.w + a1.y + c1.y + acc.w);
        if (r < NUM_USERS) {
            float4 l = ((const float4*)(ul + (size_t)r * EMB))[l16];
            o.x += l.x; o.y += l.y; o.z += l.z; o.w += l.w;
        }
        ((float4*)(out + (size_t)r * EMB))[l16] = o;
    }
}

// ---------------- launch ----------------
extern "C" void kernel_launch(void* const* d_in, const int* in_sizes, int n_in,
                              void* d_out, int out_size) {
    const float* user    = (const float*)d_in[0];
    const float* item    = (const float*)d_in[1];
    const float* adj_val = (const float*)d_in[2];
    const float* hv_val  = (const float*)d_in[3];
    const float* hu_val  = (const float*)d_in[4];
    const int*   adj_row = (const int*)d_in[5];
    const int*   adj_col = (const int*)d_in[6];
    const int*   hv_row  = (const int*)d_in[7];
    const int*   hv_col  = (const int*)d_in[8];
    const int*   hu_row  = (const int*)d_in[9];
    const int*   hu_col  = (const int*)d_in[10];
    float* out = (float*)d_out;

    const int E_adj = in_sizes[2];
    const int E_hv  = in_sizes[3];
    const int E_hu  = in_sizes[4];

    float* ul;
    cudaGetSymbolAddress((void**)&ul, g_ul);

    const int TB = 256;
    const int na4 = (E_adj + 3) / 4;
    const int nv4 = (E_hv + 3) / 4;
    const int nu4 = (E_hu + 3) / 4;
    const int nthreads_hist = na4 + nv4 + nu4 + NCONV;
    const int nthreads_scat = na4 + nv4 + nu4;

    // CSR build (g_cnt zeroed by previous call's k_phase3 / static init)
    k_hist_conv<<<(nthreads_hist + TB - 1) / TB, TB>>>(adj_row, hv_row, hu_row,
                                                       (const float4*)user, (const float4*)item,
                                                       E_adj, E_hv, E_hu, na4, nv4, nu4);
    k_blocksum_all<<<NB_TOT, TB>>>();
    k_scan_chunk_all<<<NB_TOT, TB>>>(E_adj, E_hv, E_hu);
    k_scatter_all<<<(nthreads_scat + TB - 1) / TB, TB>>>(adj_row, adj_col, adj_val,
                                                         hv_row, hv_col, hv_val,
                                                         hu_row, hu_col, hu_val,
                                                         E_adj, E_hv, E_hu, na4, nv4, nu4);

    // SpMM phases (chunked fp16 gathers, fp32 accumulate; proven 256,6 config)
    k_phase1<<<(NN + NBIC + 7) / 8, TB>>>();
    k_phase2<<<(NN + NUM_USERS + 7) / 8, TB>>>(ul);
    k_phase3<<<(NN + 7) / 8, TB>>>(user, item, ul, out);
}